// round 4
// baseline (speedup 1.0000x reference)
#include <cuda_runtime.h>
#include <math.h>

#define T_LEN 1024
#define NN    1022            /* templates */
#define PAD   1096            /* max smem read index is 1087 */
#define RR    0.2f

__device__ float g_ent[128];
__device__ unsigned int g_barrier;

// One 32-k chunk of 4 consecutive diagonals dbase..dbase+3 (dbase ≡ 1 mod 4).
// Pair k (k-th in chunk) lands at bit (31-k): MSB-first insertion via SHF.
// Bit = sign(|xa-xb| - Rs): match <=> negative. No predicates anywhere.
__device__ __forceinline__ void chunk_mask4(const float* __restrict__ xs, int k0, int dbase,
                                            float Rs, unsigned int m[4]) {
    const float4* __restrict__ xa4 = reinterpret_cast<const float4*>(xs + k0);
    const float4* __restrict__ w4  = reinterpret_cast<const float4*>(xs + k0 + dbase - 1);
    unsigned int a0 = 0, a1 = 0, a2 = 0, a3 = 0;
    float w[8];
    float4 t0 = w4[0];
    w[0] = t0.x; w[1] = t0.y; w[2] = t0.z; w[3] = t0.w;
    #pragma unroll
    for (int q = 0; q < 8; q++) {
        float4 a  = xa4[q];
        float4 tn = w4[q + 1];
        w[4] = tn.x; w[5] = tn.y; w[6] = tn.z; w[7] = tn.w;
        float av[4] = {a.x, a.y, a.z, a.w};
        #pragma unroll
        for (int r = 0; r < 4; r++) {
            float u0 = fabsf(av[r] - w[r + 1]) - Rs;   // diag dbase+0
            float u1 = fabsf(av[r] - w[r + 2]) - Rs;   // diag dbase+1
            float u2 = fabsf(av[r] - w[r + 3]) - Rs;   // diag dbase+2
            float u3 = fabsf(av[r] - w[r + 4]) - Rs;   // diag dbase+3
            a0 = __funnelshift_l(__float_as_uint(u0), a0, 1);
            a1 = __funnelshift_l(__float_as_uint(u1), a1, 1);
            a2 = __funnelshift_l(__float_as_uint(u2), a2, 1);
            a3 = __funnelshift_l(__float_as_uint(u3), a3, 1);
        }
        w[0] = w[4]; w[1] = w[5]; w[2] = w[6]; w[3] = w[7];
    }
    m[0] = a0; m[1] = a1; m[2] = a2; m[3] = a3;
}

// Count m/m1 matches for chunks [c0, c1) of diagonals dbase..dbase+3.
// Diagonal s has Lbase - s valid pairs. MSB-first bit order:
//   pair k+1 of bit j(=pair k) sits at bit j-1 -> S = funnelshift_l(Bnext, Bcur, sh).
__device__ __forceinline__ void process_range(const float* __restrict__ xs,
                                              int dbase, int Lbase, int c0, int c1, float Rs,
                                              unsigned int& cm, unsigned int& cm1) {
    if (c0 >= c1) return;
    unsigned int Bc[4], Bn[4];
    chunk_mask4(xs, 32 * c0, dbase, Rs, Bc);
    for (int c = c0; c < c1; c++) {
        chunk_mask4(xs, 32 * (c + 1), dbase, Rs, Bn);
        if (32 * c + 35 <= Lbase) {          // all 4 diagonals full in this chunk
            #pragma unroll
            for (int s = 0; s < 4; s++) {
                unsigned int S1 = __funnelshift_l(Bn[s], Bc[s], 1);
                unsigned int S2 = __funnelshift_l(Bn[s], Bc[s], 2);
                unsigned int mm = Bc[s] & S1;
                cm  += __popc(mm);
                cm1 += __popc(mm & S2);
            }
        } else {                              // diagonal-end chunk: keep top `rem` bits
            #pragma unroll
            for (int s = 0; s < 4; s++) {
                int rem = Lbase - s - 32 * c;
                unsigned int mask = (rem >= 32) ? 0xffffffffu
                                  : ((rem <= 0) ? 0u : (0xffffffffu << (32 - rem)));
                unsigned int S1 = __funnelshift_l(Bn[s], Bc[s], 1);
                unsigned int S2 = __funnelshift_l(Bn[s], Bc[s], 2);
                unsigned int mm = Bc[s] & S1 & mask;
                cm  += __popc(mm);
                cm1 += __popc(mm & S2);
            }
        }
        Bc[0] = Bn[0]; Bc[1] = Bn[1]; Bc[2] = Bn[2]; Bc[3] = Bn[3];
    }
}

__global__ __launch_bounds__(1024, 1)
void sampen_kernel(const float* __restrict__ pred, const float* __restrict__ tgt,
                   float* __restrict__ out) {
    __shared__ __align__(16) float xs[PAD];
    __shared__ double redA[32], redB[32];
    __shared__ unsigned int redc[32], redc1[32];
    __shared__ float s_thresh;

    const int s   = blockIdx.x;
    const int tid = threadIdx.x;
    const float* src = (s < 64) ? (pred + (size_t)s * T_LEN)
                                : (tgt  + (size_t)(s - 64) * T_LEN);

    // ---- load raw signal + zero pad ----
    float v = src[tid];
    xs[tid] = v;
    for (int i = T_LEN + tid; i < PAD; i += 1024) xs[i] = 0.0f;

    // ---- std (ddof=1) in double; mean cancels inside |xi-xj|:
    //      scaled threshold Rs = R * (std + eps) ----
    double ls  = (double)v;
    double ls2 = (double)v * (double)v;
    #pragma unroll
    for (int o = 16; o > 0; o >>= 1) {
        ls  += __shfl_down_sync(0xffffffffu, ls,  o);
        ls2 += __shfl_down_sync(0xffffffffu, ls2, o);
    }
    if ((tid & 31) == 0) { redA[tid >> 5] = ls; redB[tid >> 5] = ls2; }
    __syncthreads();
    if (tid == 0) {
        double S = 0.0, S2 = 0.0;
        #pragma unroll
        for (int w = 0; w < 32; w++) { S += redA[w]; S2 += redB[w]; }
        double var = (S2 - S * S / (double)T_LEN) / (double)(T_LEN - 1);
        double sd  = sqrt(var);
        s_thresh = (float)((double)RR * (sd + 1e-8));
    }
    __syncthreads();
    const float Rs = s_thresh;

    // ---- upper-triangle counting: 4-diagonal groups, paired + 8-way split-k ----
    // Group g covers diagonals 4g+1..4g+4. Pair (P, 255-P): C_A + C_B == 33 chunks.
    // Thread = (P = tid & 127, slot = tid >> 7); slot owns [g0, g1) of the 33 chunks.
    const int P  = tid & 127;
    const int sg = tid >> 7;
    const int dA = 4 * P + 1;
    const int LA = NN - dA;            // 1021 - 4P
    const int dB = 1021 - 4 * P;       // group 255-P
    const int LB = NN - dB;            // 4P + 1
    const int CA = (LA + 31) >> 5;
    const int C  = CA + ((LB + 31) >> 5);   // == 33
    const int g0 = (sg * C) >> 3;
    const int g1 = ((sg + 1) * C) >> 3;

    unsigned int cm = 0, cm1 = 0;
    {
        int a0 = g0, a1 = (g1 < CA) ? g1 : CA;
        process_range(xs, dA, LA, a0, a1, Rs, cm, cm1);
        int b0 = (g0 > CA ? g0 : CA) - CA;
        int b1 = g1 - CA;
        process_range(xs, dB, LB, b0, b1, Rs, cm, cm1);
    }

    // ---- reduce counts ----
    #pragma unroll
    for (int o = 16; o > 0; o >>= 1) {
        cm  += __shfl_down_sync(0xffffffffu, cm,  o);
        cm1 += __shfl_down_sync(0xffffffffu, cm1, o);
    }
    if ((tid & 31) == 0) { redc[tid >> 5] = cm; redc1[tid >> 5] = cm1; }
    __syncthreads();

    if (tid == 0) {
        unsigned int tm = 0, tm1 = 0;
        #pragma unroll
        for (int w = 0; w < 32; w++) { tm += redc[w]; tm1 += redc1[w]; }
        // symmetric matrix + zero diagonal: matches = NN + 2*upper
        unsigned int matches_m  = (unsigned int)NN + 2u * tm;
        unsigned int matches_m1 = (unsigned int)NN + 2u * tm1;
        float ratio = (float)matches_m1 / (float)matches_m;   // matches_m >= NN > 0
        ratio = fmaxf(ratio, 1e-30f);
        g_ent[s] = -logf(ratio);

        // ---- fused finalize: last block computes the MSE ----
        __threadfence();
        unsigned int old = atomicAdd(&g_barrier, 1);
        if (old == 127u) {
            g_barrier = 0;            // reset for next graph replay
            __threadfence();          // make all g_ent writes visible
            float acc = 0.0f;
            #pragma unroll
            for (int i = 0; i < 64; i++) {
                float dp = __ldcg(&g_ent[i]);
                float dt = __ldcg(&g_ent[64 + i]);
                float dd = dp - dt;
                acc += dd * dd;
            }
            out[0] = acc * (1.0f / 64.0f);
        }
    }
}

extern "C" void kernel_launch(void* const* d_in, const int* in_sizes, int n_in,
                              void* d_out, int out_size) {
    const float* pred = (const float*)d_in[0];
    const float* tgt  = (const float*)d_in[1];
    float* out = (float*)d_out;
    sampen_kernel<<<128, 1024>>>(pred, tgt, out);
}